// round 8
// baseline (speedup 1.0000x reference)
#include <cuda_runtime.h>
#include <cstdint>

#define RES0 2048
#define RES1 1024
#define NPTS 2097152

// g0: dup-pair table, entry (y,x) = codes(y,x) | codes(y,min(x+1,RES-1))<<32.
// 32 MB. Sample does two LDG.64 (rows y0, y0+1).
__device__ uint64_t g_pair0[(size_t)RES0 * RES0];
// g1: quad table, entry (y,x) = codes of the 4 corners (clamped). 16 MB, one LDG.128.
__device__ uint4 g_quad1[(size_t)RES1 * RES1];

// codes = clip(round((v + 15/32) * 16), 0, 15); round-half-even matches jnp.round.
__device__ __forceinline__ uint32_t quant_code(float v) {
    float t = __fmul_rn(__fadd_rn(v, 0.46875f), 16.0f);
    int c = __float2int_rn(t);
    return (uint32_t)max(0, min(15, c));
}

// Exact dequant of nibble i: c/16 - 15/32. SHF + LOP3 + FADD.
__device__ __forceinline__ float dec(uint32_t p, int i) {
    uint32_t t = (i < 5) ? (p << (19 - 4 * i)) : (p >> (4 * i - 19));
    uint32_t u = (t & 0x00780000u) | 0x3F800000u;
    return __uint_as_float(u) - 1.46875f;
}

// ---------------- fused pack: both grids in ONE launch ----------------------
__device__ __forceinline__ void pack_body0(const float* __restrict__ g, int blk) {
    __shared__ uint32_t sc[16][33];
    int bx = (blk % (RES0 / 32)) * 32;
    int by = (blk / (RES0 / 32)) * 16;
    int tid = threadIdx.x;

    for (int p = tid; p < 16 * 33; p += 512) {
        int ly = p / 33, lx = p - ly * 33;
        int gx = min(bx + lx, RES0 - 1);
        size_t base = (size_t)(by + ly) * RES0 + gx;
        uint32_t pk = 0;
#pragma unroll
        for (int c = 0; c < 8; c++) {
            float v = __ldcs(g + (size_t)c * RES0 * RES0 + base);
            pk |= quant_code(v) << (4 * c);
        }
        sc[ly][lx] = pk;
    }
    __syncthreads();

    int lx = tid & 31, ly = tid >> 5;
    uint64_t e = (uint64_t)sc[ly][lx] | ((uint64_t)sc[ly][lx + 1] << 32);
    g_pair0[(size_t)(by + ly) * RES0 + bx + lx] = e;
}

__device__ __forceinline__ void pack_body1(const float* __restrict__ g, int blk) {
    __shared__ uint32_t sc[17][33];
    int bx = (blk % (RES1 / 32)) * 32;
    int by = (blk / (RES1 / 32)) * 16;
    int tid = threadIdx.x;

    for (int p = tid; p < 17 * 33; p += 512) {
        int ly = p / 33, lx = p - ly * 33;
        int gx = min(bx + lx, RES1 - 1);
        int gy = min(by + ly, RES1 - 1);
        size_t base = (size_t)gy * RES1 + gx;
        uint32_t pk = 0;
#pragma unroll
        for (int c = 0; c < 8; c++) {
            float v = __ldcs(g + (size_t)c * RES1 * RES1 + base);
            pk |= quant_code(v) << (4 * c);
        }
        sc[ly][lx] = pk;
    }
    __syncthreads();

    int lx = tid & 31, ly = tid >> 5;
    g_quad1[(size_t)(by + ly) * RES1 + bx + lx] =
        make_uint4(sc[ly][lx], sc[ly][lx + 1], sc[ly + 1][lx], sc[ly + 1][lx + 1]);
}

#define NBLK0 ((RES0 / 32) * (RES0 / 16))   // 8192
#define NBLK1 ((RES1 / 32) * (RES1 / 16))   // 2048

__global__ __launch_bounds__(512) void pack_all(const float* __restrict__ g0,
                                                const float* __restrict__ g1) {
    int b = blockIdx.x;
    if (b < NBLK0) pack_body0(g0, b);
    else           pack_body1(g1, b - NBLK0);
}

// ---------------- sample: 2 points/thread, 6 gathers in flight --------------
__global__ __launch_bounds__(256) void sample_kernel(const float4* __restrict__ uv4,
                                                     float* __restrict__ out) {
    // Per-warp staging: 64 points x 12-word slots (24 KB/block).
    // Slot map: point A (even) -> slot lane, point B (odd) -> slot 32+lane
    // keeps STS.128 at stride 12 conflict-free.
    __shared__ __align__(16) float sbuf[8 * 64 * 12];

    int tid = threadIdx.x;
    int lane = tid & 31;
    int warp = tid >> 5;

    // This thread's two adjacent points: 2*pi, 2*pi+1.
    int pi = blockIdx.x * 256 + tid;
    float4 u = __ldcs(&uv4[pi]);

    float uxs[2] = {u.x, u.z};
    float uys[2] = {u.y, u.w};

    uint64_t e_top[2], e_bot[2];
    uint4 q1v[2];
    int qx0v[2], qy0v[2];
    float ixv[2], iyv[2];

    // Phase 1: indices + issue all 6 gathers (max MLP before any consume).
#pragma unroll
    for (int j = 0; j < 2; j++) {
        float ux = uxs[j], uy = uys[j];
        // feat0: pos = uv*2048 - 0.5 ; x0 = clip(floor(pos), 0, 2046)
        float px = fmaf(ux, 2048.0f, -0.5f);
        float py = fmaf(uy, 2048.0f, -0.5f);
        int x0 = min(max((int)floorf(px), 0), RES0 - 2);
        int y0 = min(max((int)floorf(py), 0), RES0 - 2);
        // feat1: ix = u*1024 - 0.5 (== grid_sample formula, exact)
        float ix = fmaf(ux, 1024.0f, -0.5f);
        float iy = fmaf(uy, 1024.0f, -0.5f);
        float fx0 = floorf(ix), fy0 = floorf(iy);
        int qx0 = (int)fx0;
        int qy0 = (int)fy0;
        int cx = max(qx0, 0);
        int cy = max(qy0, 0);

        const uint64_t* r0 = g_pair0 + (size_t)y0 * RES0 + x0;
        e_top[j] = __ldg(r0);
        e_bot[j] = __ldg(r0 + RES0);
        q1v[j] = __ldg(&g_quad1[(size_t)cy * RES1 + cx]);

        ixv[j] = ix; iyv[j] = iy;
        qx0v[j] = qx0; qy0v[j] = qy0;
    }

    // Phase 2: compute + stage each point.
#pragma unroll
    for (int j = 0; j < 2; j++) {
        float ix = ixv[j], iy = iyv[j];
        int qx0 = qx0v[j], qy0 = qy0v[j];
        uint4 q1 = q1v[j];

        float fx0 = floorf(ix), fy0 = floorf(iy);
        float wx1 = __fsub_rn(ix, fx0), wx0 = __fsub_rn(1.0f, wx1);
        float wy1 = __fsub_rn(iy, fy0), wy0 = __fsub_rn(1.0f, wy1);
        float wx0m = (qx0 >= 0) ? wx0 : 0.0f;
        float wx1m = (qx0 + 1 <= RES1 - 1) ? wx1 : 0.0f;
        float wy0m = (qy0 >= 0) ? wy0 : 0.0f;
        float wy1m = (qy0 + 1 <= RES1 - 1) ? wy1 : 0.0f;
        float w00 = wx0m * wy0m;
        float w10 = wx1m * wy0m;
        float w01 = wx0m * wy1m;
        float w11 = wx1m * wy1m;

        uint32_t p00 = q1.x;
        uint32_t p10 = (qx0 < 0) ? q1.x : q1.y;
        uint32_t p01 = (qy0 < 0) ? q1.x : q1.z;
        uint32_t p11 = (qy0 < 0) ? ((qx0 < 0) ? q1.x : q1.y)
                                 : ((qx0 < 0) ? q1.z : q1.w);

        float ff[8];
#pragma unroll
        for (int c = 0; c < 8; c++) {
            float s = dec(p00, c) * w00;
            s = fmaf(dec(p10, c), w10, s);
            s = fmaf(dec(p01, c), w01, s);
            s = fmaf(dec(p11, c), w11, s);
            ff[c] = s;
        }

        uint4 q0 = make_uint4((uint32_t)e_top[j], (uint32_t)(e_top[j] >> 32),
                              (uint32_t)e_bot[j], (uint32_t)(e_bot[j] >> 32));
        float* s = &sbuf[warp * (64 * 12) + (j * 32 + lane) * 12];
        *(uint4*)s = q0;
        *(float4*)(s + 4) = make_float4(ff[0], ff[1], ff[2], ff[3]);
        *(float4*)(s + 8) = make_float4(ff[4], ff[5], ff[6], ff[7]);
    }
    __syncwarp();

    // Phase 3: coalesced readout of the warp's 64-point region.
    const float* ws = &sbuf[warp * (64 * 12)];
    float4* go = reinterpret_cast<float4*>(out) +
                 (size_t)(blockIdx.x * 512 + warp * 64) * 10;
#pragma unroll
    for (int k = 0; k < 20; k++) {
        int wo = lane + 32 * k;        // float4 index within 640
        int pp = wo / 10;              // point index 0..63 in region
        int jj = wo - pp * 10;
        int slot = (pp >> 1) + ((pp & 1) << 5);  // invert interleave map
        const float* sp = ws + slot * 12;
        float4 v;
        if (jj < 8) {
            uint32_t code = __float_as_uint(sp[jj >> 1]);
            int cb = (jj & 1) * 4;
            v = make_float4(dec(code, cb), dec(code, cb + 1),
                            dec(code, cb + 2), dec(code, cb + 3));
        } else {
            v = *(const float4*)(sp + 4 + (jj - 8) * 4);
        }
        __stcs(&go[wo], v);
    }
}

extern "C" void kernel_launch(void* const* d_in, const int* in_sizes, int n_in,
                              void* d_out, int out_size) {
    const float4* uv4 = (const float4*)d_in[0];
    const float*  g0  = (const float*)d_in[1];
    const float*  g1  = (const float*)d_in[2];

    pack_all<<<NBLK0 + NBLK1, 512>>>(g0, g1);
    sample_kernel<<<NPTS / 512, 256>>>(uv4, (float*)d_out);
}

// round 9
// speedup vs baseline: 1.4769x; 1.4769x over previous
#include <cuda_runtime.h>
#include <cstdint>

#define RES0 2048
#define RES1 1024
#define NPTS 2097152

// g0: dup-pair table, entry (y,x) = codes(y,x) | codes(y,min(x+1,RES-1))<<32. 32 MB.
__device__ uint64_t g_pair0[(size_t)RES0 * RES0];
// g1: quad table, entry (y,x) = codes of 4 clamped corners. 16 MB.
__device__ uint4 g_quad1[(size_t)RES1 * RES1];

__device__ __forceinline__ uint32_t quant_code(float v) {
    float t = __fmul_rn(__fadd_rn(v, 0.46875f), 16.0f);
    int c = __float2int_rn(t);
    return (uint32_t)max(0, min(15, c));
}

// Exact dequant of nibble i: c/16 - 15/32.
__device__ __forceinline__ float dec(uint32_t p, int i) {
    uint32_t t = (i < 5) ? (p << (19 - 4 * i)) : (p >> (4 * i - 19));
    uint32_t u = (t & 0x00780000u) | 0x3F800000u;
    return __uint_as_float(u) - 1.46875f;
}

// ---------------- fused pack (unchanged from R7) ----------------------------
__device__ __forceinline__ void pack_body0(const float* __restrict__ g, int blk) {
    __shared__ uint32_t sc[16][33];
    int bx = (blk % (RES0 / 32)) * 32;
    int by = (blk / (RES0 / 32)) * 16;
    int tid = threadIdx.x;

    for (int p = tid; p < 16 * 33; p += 512) {
        int ly = p / 33, lx = p - ly * 33;
        int gx = min(bx + lx, RES0 - 1);
        size_t base = (size_t)(by + ly) * RES0 + gx;
        uint32_t pk = 0;
#pragma unroll
        for (int c = 0; c < 8; c++) {
            float v = __ldcs(g + (size_t)c * RES0 * RES0 + base);
            pk |= quant_code(v) << (4 * c);
        }
        sc[ly][lx] = pk;
    }
    __syncthreads();

    int lx = tid & 31, ly = tid >> 5;
    uint64_t e = (uint64_t)sc[ly][lx] | ((uint64_t)sc[ly][lx + 1] << 32);
    g_pair0[(size_t)(by + ly) * RES0 + bx + lx] = e;
}

__device__ __forceinline__ void pack_body1(const float* __restrict__ g, int blk) {
    __shared__ uint32_t sc[17][33];
    int bx = (blk % (RES1 / 32)) * 32;
    int by = (blk / (RES1 / 32)) * 16;
    int tid = threadIdx.x;

    for (int p = tid; p < 17 * 33; p += 512) {
        int ly = p / 33, lx = p - ly * 33;
        int gx = min(bx + lx, RES1 - 1);
        int gy = min(by + ly, RES1 - 1);
        size_t base = (size_t)gy * RES1 + gx;
        uint32_t pk = 0;
#pragma unroll
        for (int c = 0; c < 8; c++) {
            float v = __ldcs(g + (size_t)c * RES1 * RES1 + base);
            pk |= quant_code(v) << (4 * c);
        }
        sc[ly][lx] = pk;
    }
    __syncthreads();

    int lx = tid & 31, ly = tid >> 5;
    g_quad1[(size_t)(by + ly) * RES1 + bx + lx] =
        make_uint4(sc[ly][lx], sc[ly][lx + 1], sc[ly + 1][lx], sc[ly + 1][lx + 1]);
}

#define NBLK0 ((RES0 / 32) * (RES0 / 16))
#define NBLK1 ((RES1 / 32) * (RES1 / 16))

__global__ __launch_bounds__(512) void pack_all(const float* __restrict__ g0,
                                                const float* __restrict__ g1) {
    int b = blockIdx.x;
    if (b < NBLK0) pack_body0(g0, b);
    else           pack_body1(g1, b - NBLK0);
}

// ---------------- sample: 2 pts/thread, 64-reg budget, scalar liveness ------
__global__ __launch_bounds__(256, 4) void sample_kernel(const float4* __restrict__ uv4,
                                                        float* __restrict__ out) {
    __shared__ __align__(16) float sbuf[8 * 64 * 12];

    int tid = threadIdx.x;
    int lane = tid & 31;
    int warp = tid >> 5;

    int pi = blockIdx.x * 256 + tid;
    float4 u = __ldcs(&uv4[pi]);   // two adjacent points

    // ---- point A indices ----
    float pxA = fmaf(u.x, 2048.0f, -0.5f);
    float pyA = fmaf(u.y, 2048.0f, -0.5f);
    int x0A = min(max((int)floorf(pxA), 0), RES0 - 2);
    int y0A = min(max((int)floorf(pyA), 0), RES0 - 2);
    float ixA = fmaf(u.x, 1024.0f, -0.5f);
    float iyA = fmaf(u.y, 1024.0f, -0.5f);
    float fxA = floorf(ixA), fyA = floorf(iyA);
    int qxA = (int)fxA, qyA = (int)fyA;
    // ---- point B indices ----
    float pxB = fmaf(u.z, 2048.0f, -0.5f);
    float pyB = fmaf(u.w, 2048.0f, -0.5f);
    int x0B = min(max((int)floorf(pxB), 0), RES0 - 2);
    int y0B = min(max((int)floorf(pyB), 0), RES0 - 2);
    float ixB = fmaf(u.z, 1024.0f, -0.5f);
    float iyB = fmaf(u.w, 1024.0f, -0.5f);
    float fxB = floorf(ixB), fyB = floorf(iyB);
    int qxB = (int)fxB, qyB = (int)fyB;

    // ---- 6 independent gathers, issued back-to-back ----
    const uint64_t* rA = g_pair0 + (size_t)y0A * RES0 + x0A;
    const uint64_t* rB = g_pair0 + (size_t)y0B * RES0 + x0B;
    uint64_t tA = __ldg(rA);
    uint64_t bA = __ldg(rA + RES0);
    uint64_t tB = __ldg(rB);
    uint64_t bB = __ldg(rB + RES0);
    uint4 q1A = __ldg(&g_quad1[(size_t)max(qyA, 0) * RES1 + max(qxA, 0)]);
    uint4 q1B = __ldg(&g_quad1[(size_t)max(qyB, 0) * RES1 + max(qxB, 0)]);

    // ---- per-point compute + stage ----
#pragma unroll
    for (int j = 0; j < 2; j++) {
        float ix = j ? ixB : ixA;
        float iy = j ? iyB : iyA;
        float fx0 = j ? fxB : fxA;
        float fy0 = j ? fyB : fyA;
        int qx0 = j ? qxB : qxA;
        int qy0 = j ? qyB : qyA;
        uint4 q1 = j ? q1B : q1A;
        uint64_t et = j ? tB : tA;
        uint64_t eb = j ? bB : bA;

        float wx1 = __fsub_rn(ix, fx0), wx0 = __fsub_rn(1.0f, wx1);
        float wy1 = __fsub_rn(iy, fy0), wy0 = __fsub_rn(1.0f, wy1);
        float wx0m = (qx0 >= 0) ? wx0 : 0.0f;
        float wx1m = (qx0 + 1 <= RES1 - 1) ? wx1 : 0.0f;
        float wy0m = (qy0 >= 0) ? wy0 : 0.0f;
        float wy1m = (qy0 + 1 <= RES1 - 1) ? wy1 : 0.0f;
        float w00 = wx0m * wy0m;
        float w10 = wx1m * wy0m;
        float w01 = wx0m * wy1m;
        float w11 = wx1m * wy1m;

        uint32_t p00 = q1.x;
        uint32_t p10 = (qx0 < 0) ? q1.x : q1.y;
        uint32_t p01 = (qy0 < 0) ? q1.x : q1.z;
        uint32_t p11 = (qy0 < 0) ? ((qx0 < 0) ? q1.x : q1.y)
                                 : ((qx0 < 0) ? q1.z : q1.w);

        float ff[8];
#pragma unroll
        for (int c = 0; c < 8; c++) {
            float s = dec(p00, c) * w00;
            s = fmaf(dec(p10, c), w10, s);
            s = fmaf(dec(p01, c), w01, s);
            s = fmaf(dec(p11, c), w11, s);
            ff[c] = s;
        }

        float* s = &sbuf[warp * (64 * 12) + (j * 32 + lane) * 12];
        *(uint4*)s = make_uint4((uint32_t)et, (uint32_t)(et >> 32),
                                (uint32_t)eb, (uint32_t)(eb >> 32));
        *(float4*)(s + 4) = make_float4(ff[0], ff[1], ff[2], ff[3]);
        *(float4*)(s + 8) = make_float4(ff[4], ff[5], ff[6], ff[7]);
    }
    __syncwarp();

    // ---- coalesced readout of the warp's 64-point region ----
    const float* ws = &sbuf[warp * (64 * 12)];
    float4* go = reinterpret_cast<float4*>(out) +
                 (size_t)(blockIdx.x * 512 + warp * 64) * 10;
#pragma unroll
    for (int k = 0; k < 20; k++) {
        int wo = lane + 32 * k;
        int pp = wo / 10;
        int jj = wo - pp * 10;
        int slot = (pp >> 1) + ((pp & 1) << 5);
        const float* sp = ws + slot * 12;
        float4 v;
        if (jj < 8) {
            uint32_t code = __float_as_uint(sp[jj >> 1]);
            int cb = (jj & 1) * 4;
            v = make_float4(dec(code, cb), dec(code, cb + 1),
                            dec(code, cb + 2), dec(code, cb + 3));
        } else {
            v = *(const float4*)(sp + 4 + (jj - 8) * 4);
        }
        __stcs(&go[wo], v);
    }
}

extern "C" void kernel_launch(void* const* d_in, const int* in_sizes, int n_in,
                              void* d_out, int out_size) {
    const float4* uv4 = (const float4*)d_in[0];
    const float*  g0  = (const float*)d_in[1];
    const float*  g1  = (const float*)d_in[2];

    pack_all<<<NBLK0 + NBLK1, 512>>>(g0, g1);
    sample_kernel<<<NPTS / 512, 256>>>(uv4, (float*)d_out);
}

// round 10
// speedup vs baseline: 1.4960x; 1.0129x over previous
#include <cuda_runtime.h>
#include <cstdint>

#define RES0 2048
#define RES1 1024
#define NPTS 2097152

// g0: dup-pair table, entry (y,x) = codes(y,x) | codes(y,min(x+1,RES-1))<<32. 32 MB.
__device__ uint64_t g_pair0[(size_t)RES0 * RES0];
// g1: quad table, entry (y,x) = codes of 4 clamped corners. 16 MB.
__device__ uint4 g_quad1[(size_t)RES1 * RES1];
// Total 48 MB; with the output stream kept OUT of L2 (stwt), these stay resident.

// codes = clip(round((v + 15/32) * 16), 0, 15); round-half-even matches jnp.round.
__device__ __forceinline__ uint32_t quant_code(float v) {
    float t = __fmul_rn(__fadd_rn(v, 0.46875f), 16.0f);
    int c = __float2int_rn(t);
    return (uint32_t)max(0, min(15, c));
}

// Exact dequant of nibble i: c/16 - 15/32.
__device__ __forceinline__ float dec(uint32_t p, int i) {
    uint32_t t = (i < 5) ? (p << (19 - 4 * i)) : (p >> (4 * i - 19));
    uint32_t u = (t & 0x00780000u) | 0x3F800000u;
    return __uint_as_float(u) - 1.46875f;
}

// ---------------- fused pack: both grids in ONE launch ----------------------
__device__ __forceinline__ void pack_body0(const float* __restrict__ g, int blk) {
    __shared__ uint32_t sc[16][33];
    int bx = (blk % (RES0 / 32)) * 32;
    int by = (blk / (RES0 / 32)) * 16;
    int tid = threadIdx.x;

    for (int p = tid; p < 16 * 33; p += 512) {
        int ly = p / 33, lx = p - ly * 33;
        int gx = min(bx + lx, RES0 - 1);
        size_t base = (size_t)(by + ly) * RES0 + gx;
        uint32_t pk = 0;
#pragma unroll
        for (int c = 0; c < 8; c++) {
            float v = __ldcs(g + (size_t)c * RES0 * RES0 + base);
            pk |= quant_code(v) << (4 * c);
        }
        sc[ly][lx] = pk;
    }
    __syncthreads();

    int lx = tid & 31, ly = tid >> 5;
    uint64_t e = (uint64_t)sc[ly][lx] | ((uint64_t)sc[ly][lx + 1] << 32);
    g_pair0[(size_t)(by + ly) * RES0 + bx + lx] = e;
}

__device__ __forceinline__ void pack_body1(const float* __restrict__ g, int blk) {
    __shared__ uint32_t sc[17][33];
    int bx = (blk % (RES1 / 32)) * 32;
    int by = (blk / (RES1 / 32)) * 16;
    int tid = threadIdx.x;

    for (int p = tid; p < 17 * 33; p += 512) {
        int ly = p / 33, lx = p - ly * 33;
        int gx = min(bx + lx, RES1 - 1);
        int gy = min(by + ly, RES1 - 1);
        size_t base = (size_t)gy * RES1 + gx;
        uint32_t pk = 0;
#pragma unroll
        for (int c = 0; c < 8; c++) {
            float v = __ldcs(g + (size_t)c * RES1 * RES1 + base);
            pk |= quant_code(v) << (4 * c);
        }
        sc[ly][lx] = pk;
    }
    __syncthreads();

    int lx = tid & 31, ly = tid >> 5;
    g_quad1[(size_t)(by + ly) * RES1 + bx + lx] =
        make_uint4(sc[ly][lx], sc[ly][lx + 1], sc[ly + 1][lx], sc[ly + 1][lx + 1]);
}

#define NBLK0 ((RES0 / 32) * (RES0 / 16))   // 8192
#define NBLK1 ((RES1 / 32) * (RES1 / 16))   // 2048

__global__ __launch_bounds__(512) void pack_all(const float* __restrict__ g0,
                                                const float* __restrict__ g1) {
    int b = blockIdx.x;
    if (b < NBLK0) pack_body0(g0, b);
    else           pack_body1(g1, b - NBLK0);
}

// ---------------- sample: 1 pt/thread (R7), output via st.global.wt ---------
__global__ __launch_bounds__(256) void sample_kernel(const float2* __restrict__ uv,
                                                     float* __restrict__ out) {
    __shared__ __align__(16) float sbuf[8 * 32 * 12];

    int tid = threadIdx.x;
    int lane = tid & 31;
    int warp = tid >> 5;
    int i = blockIdx.x * 256 + tid;

    float2 p = __ldcs(&uv[i]);

    // feat0: pos = uv*2048 - 0.5 ; x0 = clip(floor(pos), 0, 2046)
    float px = fmaf(p.x, 2048.0f, -0.5f);
    float py = fmaf(p.y, 2048.0f, -0.5f);
    int x0 = min(max((int)floorf(px), 0), RES0 - 2);
    int y0 = min(max((int)floorf(py), 0), RES0 - 2);

    // feat1: ix = u*1024 - 0.5 (== grid_sample formula, exact)
    float ix = fmaf(p.x, 1024.0f, -0.5f);
    float iy = fmaf(p.y, 1024.0f, -0.5f);
    float fx0 = floorf(ix), fy0 = floorf(iy);
    int qx0 = (int)fx0;
    int qy0 = (int)fy0;
    int cx = max(qx0, 0);
    int cy = max(qy0, 0);

    // Three independent gathers issued up front (tables L2-resident).
    const uint64_t* r0 = g_pair0 + (size_t)y0 * RES0 + x0;
    uint64_t e_top = __ldg(r0);
    uint64_t e_bot = __ldg(r0 + RES0);
    uint4 q1 = __ldg(&g_quad1[(size_t)cy * RES1 + cx]);

    // feat1 weights (zeros-padding via weight masking).
    float wx1 = __fsub_rn(ix, fx0), wx0 = __fsub_rn(1.0f, wx1);
    float wy1 = __fsub_rn(iy, fy0), wy0 = __fsub_rn(1.0f, wy1);
    float wx0m = (qx0 >= 0) ? wx0 : 0.0f;
    float wx1m = (qx0 + 1 <= RES1 - 1) ? wx1 : 0.0f;
    float wy0m = (qy0 >= 0) ? wy0 : 0.0f;
    float wy1m = (qy0 + 1 <= RES1 - 1) ? wy1 : 0.0f;
    float w00 = wx0m * wy0m;
    float w10 = wx1m * wy0m;
    float w01 = wx0m * wy1m;
    float w11 = wx1m * wy1m;

    // Slot-select for clamped/OOB taps.
    uint32_t p00 = q1.x;
    uint32_t p10 = (qx0 < 0) ? q1.x : q1.y;
    uint32_t p01 = (qy0 < 0) ? q1.x : q1.z;
    uint32_t p11 = (qy0 < 0) ? ((qx0 < 0) ? q1.x : q1.y)
                             : ((qx0 < 0) ? q1.z : q1.w);

    // feat1: FMA accumulation (within ~1e-7 of reference order; tol 1e-3).
    float ff[8];
#pragma unroll
    for (int c = 0; c < 8; c++) {
        float s = dec(p00, c) * w00;
        s = fmaf(dec(p10, c), w10, s);
        s = fmaf(dec(p01, c), w01, s);
        s = fmaf(dec(p11, c), w11, s);
        ff[c] = s;
    }

    // Stage: raw g0 corner codes + decoded feat1 (3x STS.128 per point).
    uint4 q0 = make_uint4((uint32_t)e_top, (uint32_t)(e_top >> 32),
                          (uint32_t)e_bot, (uint32_t)(e_bot >> 32));
    float* s = &sbuf[warp * (32 * 12) + lane * 12];
    *(uint4*)s = q0;
    *(float4*)(s + 4) = make_float4(ff[0], ff[1], ff[2], ff[3]);
    *(float4*)(s + 8) = make_float4(ff[4], ff[5], ff[6], ff[7]);
    __syncwarp();

    // Coalesced readout; st.global.wt keeps the output stream OUT of L2
    // so the 48 MB of tables stay resident.
    const float* ws = &sbuf[warp * (32 * 12)];
    float4* go = reinterpret_cast<float4*>(out) +
                 (size_t)(blockIdx.x * 256 + warp * 32) * 10;
#pragma unroll
    for (int k = 0; k < 10; k++) {
        int wo = lane + 32 * k;        // float4 index within the warp's 320
        int pp = wo / 10;              // point within warp tile
        int jj = wo - pp * 10;         // float4 within point
        const float* sp = ws + pp * 12;
        float4 v;
        if (jj < 8) {
            uint32_t code = __float_as_uint(sp[jj >> 1]);  // corner jj>>1
            int cb = (jj & 1) * 4;
            v = make_float4(dec(code, cb), dec(code, cb + 1),
                            dec(code, cb + 2), dec(code, cb + 3));
        } else {
            v = *(const float4*)(sp + 4 + (jj - 8) * 4);   // staged feat1
        }
        __stwt(&go[wo], v);            // write-through, no L2 allocation
    }
}

extern "C" void kernel_launch(void* const* d_in, const int* in_sizes, int n_in,
                              void* d_out, int out_size) {
    const float2* uv = (const float2*)d_in[0];
    const float*  g0 = (const float*)d_in[1];
    const float*  g1 = (const float*)d_in[2];

    pack_all<<<NBLK0 + NBLK1, 512>>>(g0, g1);
    sample_kernel<<<NPTS / 256, 256>>>(uv, (float*)d_out);
}

// round 11
// speedup vs baseline: 1.8959x; 1.2673x over previous
#include <cuda_runtime.h>
#include <cstdint>

#define RES0 2048
#define RES1 1024
#define NPTS 2097152

// g0: plain per-texel code table (8ch x 4bit -> u32). 16 MB.
__device__ uint32_t g_code0[(size_t)RES0 * RES0];
// g1: quad table, entry (y,x) = codes of 4 clamped corners. 16 MB.
__device__ uint4 g_quad1[(size_t)RES1 * RES1];
// Total 32 MB -> comfortably L2-resident against evict-first streams.

// codes = clip(round((v + 15/32) * 16), 0, 15); round-half-even matches jnp.round.
__device__ __forceinline__ uint32_t quant_code(float v) {
    float t = __fmul_rn(__fadd_rn(v, 0.46875f), 16.0f);
    int c = __float2int_rn(t);
    return (uint32_t)max(0, min(15, c));
}

// Exact dequant of nibble i: c/16 - 15/32.
__device__ __forceinline__ float dec(uint32_t p, int i) {
    uint32_t t = (i < 5) ? (p << (19 - 4 * i)) : (p >> (4 * i - 19));
    uint32_t u = (t & 0x00780000u) | 0x3F800000u;
    return __uint_as_float(u) - 1.46875f;
}

// ---------------- fused pack: both grids in ONE launch ----------------------
// g0 body: NO halo needed (sample gathers its own 4 corners). Pure streaming
// quantize, 4 texels/thread, fully vectorized.
__device__ __forceinline__ void pack_body0(const float* __restrict__ g, int blk) {
    int i4 = (blk * 512 + threadIdx.x) * 4;
    uint32_t c0 = 0, c1 = 0, c2 = 0, c3 = 0;
#pragma unroll
    for (int ch = 0; ch < 8; ch++) {
        float4 v = __ldcs((const float4*)(g + (size_t)ch * RES0 * RES0 + i4));
        c0 |= quant_code(v.x) << (4 * ch);
        c1 |= quant_code(v.y) << (4 * ch);
        c2 |= quant_code(v.z) << (4 * ch);
        c3 |= quant_code(v.w) << (4 * ch);
    }
    *(uint4*)(g_code0 + i4) = make_uint4(c0, c1, c2, c3);
}

// g1 body: full quad (x+y halo) via smem tile.
__device__ __forceinline__ void pack_body1(const float* __restrict__ g, int blk) {
    __shared__ uint32_t sc[17][33];
    int bx = (blk % (RES1 / 32)) * 32;
    int by = (blk / (RES1 / 32)) * 16;
    int tid = threadIdx.x;

    for (int p = tid; p < 17 * 33; p += 512) {
        int ly = p / 33, lx = p - ly * 33;
        int gx = min(bx + lx, RES1 - 1);
        int gy = min(by + ly, RES1 - 1);
        size_t base = (size_t)gy * RES1 + gx;
        uint32_t pk = 0;
#pragma unroll
        for (int c = 0; c < 8; c++) {
            float v = __ldcs(g + (size_t)c * RES1 * RES1 + base);
            pk |= quant_code(v) << (4 * c);
        }
        sc[ly][lx] = pk;
    }
    __syncthreads();

    int lx = tid & 31, ly = tid >> 5;
    g_quad1[(size_t)(by + ly) * RES1 + bx + lx] =
        make_uint4(sc[ly][lx], sc[ly][lx + 1], sc[ly + 1][lx], sc[ly + 1][lx + 1]);
}

#define NBLK0 (RES0 * RES0 / 4 / 512)       // 2048
#define NBLK1 ((RES1 / 32) * (RES1 / 16))   // 2048

__global__ __launch_bounds__(512) void pack_all(const float* __restrict__ g0,
                                                const float* __restrict__ g1) {
    int b = blockIdx.x;
    if (b < NBLK0) pack_body0(g0, b);
    else           pack_body1(g1, b - NBLK0);
}

// ---------------- sample: 5 gathers/point into 32 MB resident tables --------
__global__ __launch_bounds__(256) void sample_kernel(const float2* __restrict__ uv,
                                                     float* __restrict__ out) {
    __shared__ __align__(16) float sbuf[8 * 32 * 12];

    int tid = threadIdx.x;
    int lane = tid & 31;
    int warp = tid >> 5;
    int i = blockIdx.x * 256 + tid;

    float2 p = __ldcs(&uv[i]);

    // feat0: pos = uv*2048 - 0.5 ; x0 = clip(floor(pos), 0, 2046)
    float px = fmaf(p.x, 2048.0f, -0.5f);
    float py = fmaf(p.y, 2048.0f, -0.5f);
    int x0 = min(max((int)floorf(px), 0), RES0 - 2);
    int y0 = min(max((int)floorf(py), 0), RES0 - 2);

    // feat1: ix = u*1024 - 0.5 (== grid_sample formula, exact)
    float ix = fmaf(p.x, 1024.0f, -0.5f);
    float iy = fmaf(p.y, 1024.0f, -0.5f);
    float fx0 = floorf(ix), fy0 = floorf(iy);
    int qx0 = (int)fx0;
    int qy0 = (int)fy0;
    int cx = max(qx0, 0);
    int cy = max(qy0, 0);

    // Five independent gathers issued back-to-back.
    const uint32_t* c0 = g_code0 + (size_t)y0 * RES0 + x0;
    uint32_t a00 = __ldg(c0);
    uint32_t a01 = __ldg(c0 + 1);
    uint32_t a10 = __ldg(c0 + RES0);
    uint32_t a11 = __ldg(c0 + RES0 + 1);
    uint4 q1 = __ldg(&g_quad1[(size_t)cy * RES1 + cx]);

    // feat1 weights (zeros-padding via weight masking).
    float wx1 = __fsub_rn(ix, fx0), wx0 = __fsub_rn(1.0f, wx1);
    float wy1 = __fsub_rn(iy, fy0), wy0 = __fsub_rn(1.0f, wy1);
    float wx0m = (qx0 >= 0) ? wx0 : 0.0f;
    float wx1m = (qx0 + 1 <= RES1 - 1) ? wx1 : 0.0f;
    float wy0m = (qy0 >= 0) ? wy0 : 0.0f;
    float wy1m = (qy0 + 1 <= RES1 - 1) ? wy1 : 0.0f;
    float w00 = wx0m * wy0m;
    float w10 = wx1m * wy0m;
    float w01 = wx0m * wy1m;
    float w11 = wx1m * wy1m;

    // Slot-select for clamped/OOB taps.
    uint32_t p00 = q1.x;
    uint32_t p10 = (qx0 < 0) ? q1.x : q1.y;
    uint32_t p01 = (qy0 < 0) ? q1.x : q1.z;
    uint32_t p11 = (qy0 < 0) ? ((qx0 < 0) ? q1.x : q1.y)
                             : ((qx0 < 0) ? q1.z : q1.w);

    // feat1: FMA accumulation (within ~1e-7 of reference order; tol 1e-3).
    float ff[8];
#pragma unroll
    for (int c = 0; c < 8; c++) {
        float s = dec(p00, c) * w00;
        s = fmaf(dec(p10, c), w10, s);
        s = fmaf(dec(p01, c), w01, s);
        s = fmaf(dec(p11, c), w11, s);
        ff[c] = s;
    }

    // Stage: raw g0 corner codes + decoded feat1 (3x STS.128 per point).
    float* s = &sbuf[warp * (32 * 12) + lane * 12];
    *(uint4*)s = make_uint4(a00, a01, a10, a11);
    *(float4*)(s + 4) = make_float4(ff[0], ff[1], ff[2], ff[3]);
    *(float4*)(s + 8) = make_float4(ff[4], ff[5], ff[6], ff[7]);
    __syncwarp();

    // Coalesced readout (evict-first stores protect table residency).
    const float* ws = &sbuf[warp * (32 * 12)];
    float4* go = reinterpret_cast<float4*>(out) +
                 (size_t)(blockIdx.x * 256 + warp * 32) * 10;
#pragma unroll
    for (int k = 0; k < 10; k++) {
        int wo = lane + 32 * k;        // float4 index within the warp's 320
        int pp = wo / 10;              // point within warp tile
        int jj = wo - pp * 10;         // float4 within point
        const float* sp = ws + pp * 12;
        float4 v;
        if (jj < 8) {
            uint32_t code = __float_as_uint(sp[jj >> 1]);  // corner jj>>1
            int cb = (jj & 1) * 4;
            v = make_float4(dec(code, cb), dec(code, cb + 1),
                            dec(code, cb + 2), dec(code, cb + 3));
        } else {
            v = *(const float4*)(sp + 4 + (jj - 8) * 4);   // staged feat1
        }
        __stcs(&go[wo], v);
    }
}

extern "C" void kernel_launch(void* const* d_in, const int* in_sizes, int n_in,
                              void* d_out, int out_size) {
    const float2* uv = (const float2*)d_in[0];
    const float*  g0 = (const float*)d_in[1];
    const float*  g1 = (const float*)d_in[2];

    pack_all<<<NBLK0 + NBLK1, 512>>>(g0, g1);
    sample_kernel<<<NPTS / 256, 256>>>(uv, (float*)d_out);
}